// round 5
// baseline (speedup 1.0000x reference)
#include <cuda_runtime.h>
#include <cstdint>

// PackedViterbi (logsumexp semiring) forward.
// theta: [T=256, B=32, S=128, S=128] fp32.  out: [B=32] fp32.
//
// 16 clusters x 8 CTAs. Each cluster owns TWO batches; each CTA holds 16 rows
// of each. Warps 0-3 run batch A, warps 4-7 run batch B as fully independent
// pipelines (own cp.async ring, own tagged DSMEM V slots, named barriers).
// Each SMSP carries one A-warp + one B-warp, so one chain's DSMEM transit
// hides behind the other chain's compute.

#define NT    256
#define NB    32
#define NS    128
#define CLU   8      // CTAs per cluster
#define RPB   16     // rows per CTA per batch
#define NTHR  256
#define TILEH (RPB * NS * 4)   // 8192 bytes per half per step
#define PIPE  6
#define DIST  4
#define LOG2E 1.4426950408889634f
#define FULLM 0xffffffffu

static __device__ __forceinline__ float ex2f_(float x) {
    float y; asm("ex2.approx.ftz.f32 %0, %1;" : "=f"(y) : "f"(x)); return y;
}
static __device__ __forceinline__ float lg2f_(float x) {
    float y; asm("lg2.approx.ftz.f32 %0, %1;" : "=f"(y) : "f"(x)); return y;
}
static __device__ __forceinline__ void cp16(unsigned d, const void* s) {
    asm volatile("cp.async.cg.shared.global [%0], [%1], 16;" :: "r"(d), "l"(s));
}
static __device__ __forceinline__ void st_dsmem64(unsigned daddr, unsigned long long v) {
    asm volatile("st.relaxed.cluster.shared::cluster.b64 [%0], %1;"
                 :: "r"(daddr), "l"(v) : "memory");
}
static __device__ __forceinline__ unsigned long long ld_vol64(unsigned addr) {
    unsigned long long v;
    asm volatile("ld.volatile.shared.b64 %0, [%1];" : "=l"(v) : "r"(addr));
    return v;
}
static __device__ __forceinline__ void barh(int half) {
    asm volatile("bar.sync %0, 128;" :: "r"(1 + half) : "memory");
}

extern "C" __global__ void __launch_bounds__(NTHR, 1) __cluster_dims__(CLU, 1, 1)
viterbi_fwd(const float* __restrict__ theta, float* __restrict__ out)
{
    extern __shared__ float4 ring[];   // 2 halves * PIPE * TILEH
    __shared__ __align__(8) unsigned long long sV[2][2][NS];  // [half][parity][j]
    __shared__ float sEV[2][2][NS];                           // [half][parity][j]

    const int tid  = threadIdx.x;
    const int lane = tid & 31;
    const int half = tid >> 7;          // 0: batch A (warps 0-3), 1: batch B
    const int htid = tid & 127;
    const int wh   = htid >> 5;         // warp within half, 0..3
    const int sl   = lane & 7;          // 8 lanes per row
    const int rg   = lane >> 3;
    const int rowL = (wh << 2) + rg;    // local row 0..15
    const int bid  = blockIdx.x;
    const int sub  = bid & (CLU - 1);   // cluster rank
    const int bb   = (bid >> 3) * 2 + half;   // batch for this half
    const int irow = sub * RPB + rowL;

    unsigned rbase = (unsigned)__cvta_generic_to_shared(ring)
                   + (unsigned)(half * PIPE * TILEH);
    unsigned vbase = (unsigned)__cvta_generic_to_shared(&sV[0][0][0]);

    // zero tags before any peer can write
    ((unsigned long long*)sV)[tid] = 0ull;
    ((unsigned long long*)sV)[tid + NTHR] = 0ull;
    __syncthreads();
    asm volatile("barrier.cluster.arrive.aligned;" ::: "memory");
    asm volatile("barrier.cluster.wait.aligned;"   ::: "memory");

    unsigned rV[CLU];
#pragma unroll
    for (int r = 0; r < CLU; ++r)
        asm("mapa.shared::cluster.u32 %0, %1, %2;" : "=r"(rV[r]) : "r"(vbase), "r"(r));

    const size_t tstride = (size_t)NB * NS * NS;
    const float* base = theta + ((size_t)bb * NS + (size_t)sub * RPB) * NS;

    // ---- prologue: prefetch stages 0..DIST-1 (per half) ----
#pragma unroll
    for (int s = 0; s < DIST; ++s) {
        const char* src = (const char*)(base + (size_t)s * tstride);
        unsigned dst = rbase + s * TILEH;
#pragma unroll
        for (int k2 = 0; k2 < 4; ++k2) {
            int o = (htid + k2 * 128) << 4;
            cp16(dst + o, src + o);
        }
        asm volatile("cp.async.commit_group;");
    }

    float Ea[16], Eb[16];
    float off = 0.f;

    // stage 0 -> Ea
    asm volatile("cp.async.wait_group 3;");
    {
        const float4* tp = (const float4*)((const char*)ring + half * PIPE * TILEH)
                         + rowL * (NS / 4) + sl;
        float4 a0 = tp[0], a1 = tp[8], a2 = tp[16], a3 = tp[24];
        Ea[0]  = ex2f_(a0.x * LOG2E); Ea[1]  = ex2f_(a0.y * LOG2E);
        Ea[2]  = ex2f_(a0.z * LOG2E); Ea[3]  = ex2f_(a0.w * LOG2E);
        Ea[4]  = ex2f_(a1.x * LOG2E); Ea[5]  = ex2f_(a1.y * LOG2E);
        Ea[6]  = ex2f_(a1.z * LOG2E); Ea[7]  = ex2f_(a1.w * LOG2E);
        Ea[8]  = ex2f_(a2.x * LOG2E); Ea[9]  = ex2f_(a2.y * LOG2E);
        Ea[10] = ex2f_(a2.z * LOG2E); Ea[11] = ex2f_(a2.w * LOG2E);
        Ea[12] = ex2f_(a3.x * LOG2E); Ea[13] = ex2f_(a3.y * LOG2E);
        Ea[14] = ex2f_(a3.z * LOG2E); Ea[15] = ex2f_(a3.w * LOG2E);
    }

    auto step = [&](int t, int par, float (&Ecur)[16], float (&Enext)[16]) {
        // 1. stage t+1 ready; prefetch t+DIST
        asm volatile("cp.async.wait_group 2;");
        if (t + DIST < NT) {
            const char* src = (const char*)(base + (size_t)(t + DIST) * tstride);
            unsigned dst = rbase + ((t + DIST) % PIPE) * TILEH;
#pragma unroll
            for (int k2 = 0; k2 < 4; ++k2) {
                int o = (htid + k2 * 128) << 4;
                cp16(dst + o, src + o);
            }
        }
        asm volatile("cp.async.commit_group;");

        // 2. transform stage t+1 -> Enext (off the V critical path)
        if (t + 1 < NT) {
            const float4* tp = (const float4*)
                ((const char*)ring + half * PIPE * TILEH + ((t + 1) % PIPE) * TILEH)
                + rowL * (NS / 4) + sl;
            float4 a0 = tp[0], a1 = tp[8], a2 = tp[16], a3 = tp[24];
            Enext[0]  = ex2f_(a0.x * LOG2E); Enext[1]  = ex2f_(a0.y * LOG2E);
            Enext[2]  = ex2f_(a0.z * LOG2E); Enext[3]  = ex2f_(a0.w * LOG2E);
            Enext[4]  = ex2f_(a1.x * LOG2E); Enext[5]  = ex2f_(a1.y * LOG2E);
            Enext[6]  = ex2f_(a1.z * LOG2E); Enext[7]  = ex2f_(a1.w * LOG2E);
            Enext[8]  = ex2f_(a2.x * LOG2E); Enext[9]  = ex2f_(a2.y * LOG2E);
            Enext[10] = ex2f_(a2.z * LOG2E); Enext[11] = ex2f_(a2.w * LOG2E);
            Enext[12] = ex2f_(a3.x * LOG2E); Enext[13] = ex2f_(a3.y * LOG2E);
            Enext[14] = ex2f_(a3.z * LOG2E); Enext[15] = ex2f_(a3.w * LOG2E);
        }

        // 3. poll V_t slot, build exp2 table entry (own half only)
        float r = 0.f;
        if (t == 0) {
            sEV[half][0][htid] = 1.f;
        } else {
            unsigned a = vbase + (unsigned)(((half * 2 + par) * NS + htid) * 8);
            unsigned long long v;
            do { v = ld_vol64(a); } while ((unsigned)(v >> 32) != (unsigned)t);
            sEV[half][par][htid] = ex2f_(__uint_as_float((unsigned)v));
        }
        barh(half);
        if (t > 0)
            r = __uint_as_float((unsigned)ld_vol64(
                    vbase + (unsigned)((half * 2 + par) * NS * 8)));
        off += r;

        // 4. dot product + 8-lane reduce + tagged send to all 8 ranks
        const float4* evp = (const float4*)sEV[half][par];
        float4 e0 = evp[sl], e1 = evp[sl + 8], e2 = evp[sl + 16], e3 = evp[sl + 24];
        float s0 = Ecur[0] * e0.x;
        s0 = fmaf(Ecur[1],  e0.y, s0); s0 = fmaf(Ecur[2],  e0.z, s0); s0 = fmaf(Ecur[3],  e0.w, s0);
        float s1 = Ecur[4] * e1.x;
        s1 = fmaf(Ecur[5],  e1.y, s1); s1 = fmaf(Ecur[6],  e1.z, s1); s1 = fmaf(Ecur[7],  e1.w, s1);
        float s2 = Ecur[8] * e2.x;
        s2 = fmaf(Ecur[9],  e2.y, s2); s2 = fmaf(Ecur[10], e2.z, s2); s2 = fmaf(Ecur[11], e2.w, s2);
        float s3 = Ecur[12] * e3.x;
        s3 = fmaf(Ecur[13], e3.y, s3); s3 = fmaf(Ecur[14], e3.z, s3); s3 = fmaf(Ecur[15], e3.w, s3);
        float s = (s0 + s1) + (s2 + s3);
        s += __shfl_xor_sync(FULLM, s, 1);
        s += __shfl_xor_sync(FULLM, s, 2);
        s += __shfl_xor_sync(FULLM, s, 4);

        if (sl == 0) {
            float vst = lg2f_(s) - r;
            unsigned long long pkt = ((unsigned long long)(unsigned)(t + 1) << 32)
                                   | (unsigned long long)__float_as_uint(vst);
            int k1 = (t + 1) & 1;
            unsigned voff = (unsigned)(((half * 2 + k1) * NS + irow) * 8);
#pragma unroll
            for (int rr = 0; rr < CLU; ++rr)
                st_dsmem64(rV[rr] + voff, pkt);
        }
    };

    for (int t = 0; t < NT; t += 2) {
        step(t,     0, Ea, Eb);
        step(t + 1, 1, Eb, Ea);
    }

    // ---- epilogue: V_NT (tag NT) lands in parity-0 buffer of each half ----
    {   // every CTA drains its incoming tag-NT stores (safe exit), then rank 0 reduces
        unsigned a = vbase + (unsigned)((half * 2 * NS + htid) * 8);
        unsigned long long v;
        do { v = ld_vol64(a); } while ((unsigned)(v >> 32) != (unsigned)NT);
        barh(half);
        if (sub == 0 && wh == 0) {
            float x0 = __uint_as_float((unsigned)ld_vol64(a - (htid - lane) * 8 + (lane      ) * 8));
            float x1 = __uint_as_float((unsigned)ld_vol64(a - (htid - lane) * 8 + (lane + 32 ) * 8));
            float x2 = __uint_as_float((unsigned)ld_vol64(a - (htid - lane) * 8 + (lane + 64 ) * 8));
            float x3 = __uint_as_float((unsigned)ld_vol64(a - (htid - lane) * 8 + (lane + 96 ) * 8));
            float s = ex2f_(x0) + ex2f_(x1) + ex2f_(x2) + ex2f_(x3);
#pragma unroll
            for (int o = 16; o; o >>= 1) s += __shfl_xor_sync(FULLM, s, o);
            if (lane == 0)
                out[bb] = 0.6931471805599453f * (off + lg2f_(s));
        }
    }
    asm volatile("barrier.cluster.arrive.aligned;" ::: "memory");
    asm volatile("barrier.cluster.wait.aligned;"   ::: "memory");
}

extern "C" void kernel_launch(void* const* d_in, const int* in_sizes, int n_in,
                              void* d_out, int out_size)
{
    (void)in_sizes; (void)n_in; (void)out_size;
    const float* theta = (const float*)d_in[0];
    float* out = (float*)d_out;

    cudaFuncSetAttribute(viterbi_fwd,
                         cudaFuncAttributeMaxDynamicSharedMemorySize,
                         2 * PIPE * TILEH);
    viterbi_fwd<<<NB * 4, NTHR, 2 * PIPE * TILEH>>>(theta, out);
}

// round 6
// speedup vs baseline: 1.1758x; 1.1758x over previous
#include <cuda_runtime.h>
#include <cstdint>

// PackedViterbi (logsumexp semiring) forward — exp-domain relay version.
// theta: [T=256, B=32, S=128, S=128] fp32.  out: [B=32] fp32.
//
// 32 clusters x 4 CTAs (one per batch), 256 threads per CTA, 32 rows each.
// V is relayed between steps ENTIRELY in the exp domain as tagged 8-byte
// DSMEM packets {tag, float}. Receivers poll exactly the 16 slots their dot
// needs with volatile LDS.128 (tag-sum check) — no barriers, no ex2/lg2 on
// the serial chain. Range is controlled by integer-exponent renormalization
// (common roff from slot 0, off accumulated as int). Each warp prefetches
// its own 4 theta rows with cp.async (warp-self-contained ring).

#define NT   256
#define NB   32
#define NS   128
#define SUBS 4
#define RPC  32
#define NTHR 256
#define TILE_BYTES (RPC * NS * 4)    // 16384
#define PIPE 6
#define DIST 4
#define LOG2E 1.4426950408889634f
#define FULLM 0xffffffffu

static __device__ __forceinline__ float ex2f_(float x) {
    float y; asm("ex2.approx.ftz.f32 %0, %1;" : "=f"(y) : "f"(x)); return y;
}
static __device__ __forceinline__ float lg2f_(float x) {
    float y; asm("lg2.approx.ftz.f32 %0, %1;" : "=f"(y) : "f"(x)); return y;
}
static __device__ __forceinline__ void cp16(unsigned d, const void* s) {
    asm volatile("cp.async.cg.shared.global [%0], [%1], 16;" :: "r"(d), "l"(s));
}
static __device__ __forceinline__ void st_dsmem64(unsigned daddr, unsigned long long v) {
    asm volatile("st.relaxed.cluster.shared::cluster.b64 [%0], %1;"
                 :: "r"(daddr), "l"(v) : "memory");
}

extern "C" __global__ void __launch_bounds__(NTHR, 1) __cluster_dims__(SUBS, 1, 1)
viterbi_fwd(const float* __restrict__ theta, float* __restrict__ out)
{
    extern __shared__ float4 ring[];                         // PIPE * 1024 float4
    __shared__ __align__(16) unsigned long long sV[2][NS];   // tagged exp-domain V

    const int tid  = threadIdx.x;
    const int lane = tid & 31;
    const int warp = tid >> 5;
    const int sl   = lane & 7;          // 8 lanes per row
    const int rg   = lane >> 3;
    const int rowL = (warp << 2) + rg;  // local row 0..31
    const int bid  = blockIdx.x;
    const int bb   = bid >> 2;          // batch
    const int sub  = bid & 3;           // cluster rank
    const int irow = sub * RPC + rowL;  // global state index i

    unsigned rbase = (unsigned)__cvta_generic_to_shared(ring);
    unsigned vbase = (unsigned)__cvta_generic_to_shared(&sV[0][0]);

    // zero tags before any peer can write
    ((unsigned long long*)sV)[tid] = 0ull;
    __syncthreads();
    asm volatile("barrier.cluster.arrive.aligned;" ::: "memory");
    asm volatile("barrier.cluster.wait.aligned;"   ::: "memory");

    unsigned rV[SUBS];
#pragma unroll
    for (int r = 0; r < SUBS; ++r)
        asm("mapa.shared::cluster.u32 %0, %1, %2;" : "=r"(rV[r]) : "r"(vbase), "r"(r));

    const size_t tstride = (size_t)NB * NS * NS;
    const float* base = theta + ((size_t)bb * NS + (size_t)sub * RPC) * NS;
    const int woff = warp * 2048;       // this warp's 4-row region within a tile

    // ---- prologue: each warp prefetches ITS OWN rows of stages 0..DIST-1 ----
#pragma unroll
    for (int s = 0; s < DIST; ++s) {
        const char* src = (const char*)(base + (size_t)s * tstride);
        unsigned dst = rbase + s * TILE_BYTES;
#pragma unroll
        for (int k2 = 0; k2 < 4; ++k2) {
            int o = woff + ((lane + 32 * k2) << 4);
            cp16(dst + o, src + o);
        }
        asm volatile("cp.async.commit_group;");
    }

    float Ea[16], Eb[16];
    int   off = 0;

    // stage 0 -> Ea
    asm volatile("cp.async.wait_group 3;");
    {
        const float4* tp = ring + rowL * (NS / 4) + sl;
        float4 a0 = tp[0], a1 = tp[8], a2 = tp[16], a3 = tp[24];
        Ea[0]  = ex2f_(a0.x * LOG2E); Ea[1]  = ex2f_(a0.y * LOG2E);
        Ea[2]  = ex2f_(a0.z * LOG2E); Ea[3]  = ex2f_(a0.w * LOG2E);
        Ea[4]  = ex2f_(a1.x * LOG2E); Ea[5]  = ex2f_(a1.y * LOG2E);
        Ea[6]  = ex2f_(a1.z * LOG2E); Ea[7]  = ex2f_(a1.w * LOG2E);
        Ea[8]  = ex2f_(a2.x * LOG2E); Ea[9]  = ex2f_(a2.y * LOG2E);
        Ea[10] = ex2f_(a2.z * LOG2E); Ea[11] = ex2f_(a2.w * LOG2E);
        Ea[12] = ex2f_(a3.x * LOG2E); Ea[13] = ex2f_(a3.y * LOG2E);
        Ea[14] = ex2f_(a3.z * LOG2E); Ea[15] = ex2f_(a3.w * LOG2E);
    }

    auto step = [&](int t, int par, float (&Ecur)[16], float (&Enext)[16]) {
        // 1. stage t+1 ready (own rows); prefetch own rows of t+DIST
        asm volatile("cp.async.wait_group 2;");
        if (t + DIST < NT) {
            const char* src = (const char*)(base + (size_t)(t + DIST) * tstride);
            unsigned dst = rbase + ((t + DIST) % PIPE) * TILE_BYTES;
#pragma unroll
            for (int k2 = 0; k2 < 4; ++k2) {
                int o = woff + ((lane + 32 * k2) << 4);
                cp16(dst + o, src + o);
            }
        }
        asm volatile("cp.async.commit_group;");

        // 2. transform stage t+1 -> Enext (fills the DSMEM transit window)
        if (t + 1 < NT) {
            const float4* tp = ring + ((t + 1) % PIPE) * (TILE_BYTES / 16)
                             + rowL * (NS / 4) + sl;
            float4 a0 = tp[0], a1 = tp[8], a2 = tp[16], a3 = tp[24];
            Enext[0]  = ex2f_(a0.x * LOG2E); Enext[1]  = ex2f_(a0.y * LOG2E);
            Enext[2]  = ex2f_(a0.z * LOG2E); Enext[3]  = ex2f_(a0.w * LOG2E);
            Enext[4]  = ex2f_(a1.x * LOG2E); Enext[5]  = ex2f_(a1.y * LOG2E);
            Enext[6]  = ex2f_(a1.z * LOG2E); Enext[7]  = ex2f_(a1.w * LOG2E);
            Enext[8]  = ex2f_(a2.x * LOG2E); Enext[9]  = ex2f_(a2.y * LOG2E);
            Enext[10] = ex2f_(a2.z * LOG2E); Enext[11] = ex2f_(a2.w * LOG2E);
            Enext[12] = ex2f_(a3.x * LOG2E); Enext[13] = ex2f_(a3.y * LOG2E);
            Enext[14] = ex2f_(a3.z * LOG2E); Enext[15] = ex2f_(a3.w * LOG2E);
        }

        // 3. poll the 16 exp-domain slots this lane's dot needs + slot 0
        float c;
        int roff = 0;
        if (t == 0) {
            c = ((Ecur[0] + Ecur[1]) + (Ecur[2] + Ecur[3]))
              + ((Ecur[4] + Ecur[5]) + (Ecur[6] + Ecur[7]))
              + ((Ecur[8] + Ecur[9]) + (Ecur[10] + Ecur[11]))
              + ((Ecur[12] + Ecur[13]) + (Ecur[14] + Ecur[15]));
        } else {
            const unsigned b0 = vbase + (unsigned)(par * NS * 8);
            const unsigned target = 17u * (unsigned)t;
            unsigned vb[16], v0b;
            for (;;) {
                unsigned t0, ts;
                asm volatile("ld.volatile.shared.v2.u32 {%0,%1}, [%2];"
                             : "=r"(v0b), "=r"(t0) : "r"(b0));
                ts = t0;
#pragma unroll
                for (int k = 0; k < 4; ++k) {
#pragma unroll
                    for (int h = 0; h < 2; ++h) {
                        unsigned ad = b0 + (unsigned)((32 * k + 4 * sl + 2 * h) * 8);
                        int m = 4 * k + 2 * h;
                        unsigned tA, tB;
                        asm volatile("ld.volatile.shared.v4.u32 {%0,%1,%2,%3}, [%4];"
                                     : "=r"(vb[m]), "=r"(tA), "=r"(vb[m + 1]), "=r"(tB)
                                     : "r"(ad));
                        ts += tA + tB;
                    }
                }
                if (ts == target) break;
            }
            roff = (int)((v0b >> 23) & 0xFF) - 127;

            float s0 =      Ecur[0]  * __uint_as_float(vb[0]);
            s0 = fmaf(Ecur[1],  __uint_as_float(vb[1]),  s0);
            s0 = fmaf(Ecur[2],  __uint_as_float(vb[2]),  s0);
            s0 = fmaf(Ecur[3],  __uint_as_float(vb[3]),  s0);
            float s1 =      Ecur[4]  * __uint_as_float(vb[4]);
            s1 = fmaf(Ecur[5],  __uint_as_float(vb[5]),  s1);
            s1 = fmaf(Ecur[6],  __uint_as_float(vb[6]),  s1);
            s1 = fmaf(Ecur[7],  __uint_as_float(vb[7]),  s1);
            float s2 =      Ecur[8]  * __uint_as_float(vb[8]);
            s2 = fmaf(Ecur[9],  __uint_as_float(vb[9]),  s2);
            s2 = fmaf(Ecur[10], __uint_as_float(vb[10]), s2);
            s2 = fmaf(Ecur[11], __uint_as_float(vb[11]), s2);
            float s3 =      Ecur[12] * __uint_as_float(vb[12]);
            s3 = fmaf(Ecur[13], __uint_as_float(vb[13]), s3);
            s3 = fmaf(Ecur[14], __uint_as_float(vb[14]), s3);
            s3 = fmaf(Ecur[15], __uint_as_float(vb[15]), s3);
            c = (s0 + s1) + (s2 + s3);
        }

        // 4. 8-lane reduce, exponent renorm, parallel fan-out send
        c += __shfl_xor_sync(FULLM, c, 1);
        c += __shfl_xor_sync(FULLM, c, 2);
        c += __shfl_xor_sync(FULLM, c, 4);

        if (t > 0) {
            off += roff;
            c *= __uint_as_float((unsigned)(127 - roff) << 23);   // * 2^-roff
        }
        if (sl < SUBS) {
            unsigned long long pkt = ((unsigned long long)(unsigned)(t + 1) << 32)
                                   | (unsigned long long)__float_as_uint(c);
            unsigned voff = (unsigned)((((t + 1) & 1) * NS + irow) * 8);
            st_dsmem64(rV[sl] + voff, pkt);
        }
    };

    for (int t = 0; t < NT; t += 2) {
        step(t,     0, Ea, Eb);
        step(t + 1, 1, Eb, Ea);
    }

    // ---- epilogue: drain tag NT (parity 0), then rank 0 reduces ----
    if (tid < NS) {
        unsigned ad = vbase + (unsigned)(tid * 8);
        unsigned vv, tt;
        do {
            asm volatile("ld.volatile.shared.v2.u32 {%0,%1}, [%2];"
                         : "=r"(vv), "=r"(tt) : "r"(ad));
        } while (tt != (unsigned)NT);
    }
    __syncthreads();
    if (sub == 0 && warp == 0) {
        float x0 = __uint_as_float((unsigned)sV[0][lane]);
        float x1 = __uint_as_float((unsigned)sV[0][lane + 32]);
        float x2 = __uint_as_float((unsigned)sV[0][lane + 64]);
        float x3 = __uint_as_float((unsigned)sV[0][lane + 96]);
        float s = (x0 + x1) + (x2 + x3);
#pragma unroll
        for (int o = 16; o; o >>= 1) s += __shfl_xor_sync(FULLM, s, o);
        if (lane == 0)
            out[bb] = 0.6931471805599453f * ((float)off + lg2f_(s));
    }
    asm volatile("barrier.cluster.arrive.aligned;" ::: "memory");
    asm volatile("barrier.cluster.wait.aligned;"   ::: "memory");
}

extern "C" void kernel_launch(void* const* d_in, const int* in_sizes, int n_in,
                              void* d_out, int out_size)
{
    (void)in_sizes; (void)n_in; (void)out_size;
    const float* theta = (const float*)d_in[0];
    float* out = (float*)d_out;

    cudaFuncSetAttribute(viterbi_fwd,
                         cudaFuncAttributeMaxDynamicSharedMemorySize,
                         PIPE * TILE_BYTES);
    viterbi_fwd<<<NB * SUBS, NTHR, PIPE * TILE_BYTES>>>(theta, out);
}